// round 14
// baseline (speedup 1.0000x reference)
#include <cuda_runtime.h>
#include <cuda_bf16.h>

// ---------------------------------------------------------------------------
// ENAS RNN — round 14: round-11 TMA pipeline with 2x n-tile (32 cols/CTA,
// 4 B-tiles, 512 threads, S=3) -> half the CTAs, half the A-slab broadcast
// traffic. Mainloop per-warp code identical to round 11.
// mma.sync bf16 3-term split (hi*hi + hi*lo + lo*hi), fp32 accum.
// ---------------------------------------------------------------------------

namespace {

typedef unsigned int u32;
typedef __nv_bfloat16 bf16;

constexpr int Hd = 1000;
constexpr int Bb = 64;
constexpr int Tt = 64;
constexpr int Vv = 10000;

constexpr int KP = 1024;            // padded K (8 chunks of 128)
constexpr int KC = 128;
constexpr int NCHUNK = 8;
constexpr int TILEMAT = 64 * 8 * 2048;   // 16x128 tiles, padded to 64 nblks
constexpr int DECT = 640 * 8 * 2048;     // decoder tiles, padded to 640
constexpr int HCH = 8 * 64 * 128;        // chunk-major h slab = 65536 elems

// ---------------- static device storage (zero-init = implicit padding) -----
__device__ __align__(1024) bf16 g_Whhi[11 * TILEMAT], g_Whlo[11 * TILEMAT];
__device__ __align__(1024) bf16 g_Wchi[11 * TILEMAT], g_Wclo[11 * TILEMAT];
__device__ __align__(1024) bf16 g_dect_hi[DECT], g_dect_lo[DECT];
__device__ __align__(1024) bf16 g_embhi[10000 * KP], g_emblo[10000 * KP];
__device__ __align__(1024) bf16 g_wxhe_hi[TILEMAT], g_wxhe_lo[TILEMAT];
__device__ __align__(1024) bf16 g_wxhh_hi[TILEMAT], g_wxhh_lo[TILEMAT];
__device__ __align__(1024) bf16 g_wxce_hi[TILEMAT], g_wxce_lo[TILEMAT];
__device__ __align__(1024) bf16 g_wxch_hi[TILEMAT], g_wxch_lo[TILEMAT];

__device__ __align__(1024) float g_h[12][Bb * Hd];
__device__ __align__(1024) bf16  g_hhi[12][HCH], g_hlo[12][HCH];
__device__ __align__(1024) float g_c0[Bb * Hd];
__device__ __align__(1024) float g_Ph[Tt * Bb * Hd], g_Pc[Tt * Bb * Hd];
__device__ __align__(1024) bf16  g_outshi[Tt * HCH], g_outslo[Tt * HCH];

// ---------------- helpers ---------------------------------------------------
__device__ __forceinline__ float sigmf(float x) { return 1.0f / (1.0f + expf(-x)); }

__device__ __forceinline__ float applyAct(int a, float v) {
    switch (a) {
        case 0: return fmaxf(v, 0.0f);
        case 1: return tanhf(v);
        case 2: return sigmf(v);
        default: return v;
    }
}

__device__ __forceinline__ void split1(float x, bf16& h, bf16& l) {
    h = __float2bfloat16(x);
    l = __float2bfloat16(x - __bfloat162float(h));
}
__device__ __forceinline__ u32 b2u(bf16 a, bf16 b) {
    return (u32)__bfloat16_as_ushort(a) | ((u32)__bfloat16_as_ushort(b) << 16);
}

// tile layout: matrix [rows][k<=1024] as [nblk][chunk][16 rows][128 k],
// 16B slots XOR-swizzled by (row&7) for conflict-free ldmatrix.
__device__ __forceinline__ size_t tile_off(int n, int k) {
    int within = n & 15;
    int slot = (k >> 3) & 15;
    return ((size_t)((n >> 4) * 8 + (k >> 7))) * 2048
           + within * 128 + (size_t)((slot ^ (within & 7)) << 3) + (k & 7);
}
// chunk-major swizzled A slab: [chunk][64 m][128 k]
__device__ __forceinline__ size_t chmaj_off(int m, int n) {
    int slot = ((n >> 3) & 15) ^ (m & 7);
    return ((size_t)(n >> 7) * 64 + m) * 128 + slot * 8 + (n & 7);
}

__device__ __forceinline__ void mma16816(float (&d)[4], const u32 (&a)[4], u32 b0, u32 b1) {
    asm volatile(
        "mma.sync.aligned.m16n8k16.row.col.f32.bf16.bf16.f32 "
        "{%0,%1,%2,%3}, {%4,%5,%6,%7}, {%8,%9}, {%0,%1,%2,%3};"
        : "+f"(d[0]), "+f"(d[1]), "+f"(d[2]), "+f"(d[3])
        : "r"(a[0]), "r"(a[1]), "r"(a[2]), "r"(a[3]), "r"(b0), "r"(b1));
}
__device__ __forceinline__ void ldmA(u32 a, u32 (&r)[4]) {
    asm volatile("ldmatrix.sync.aligned.m8n8.x4.shared.b16 {%0,%1,%2,%3}, [%4];"
                 : "=r"(r[0]), "=r"(r[1]), "=r"(r[2]), "=r"(r[3]) : "r"(a));
}
__device__ __forceinline__ void ldmB(u32 a, u32& b0, u32& b1) {
    asm volatile("ldmatrix.sync.aligned.m8n8.x2.shared.b16 {%0,%1}, [%2];"
                 : "=r"(b0), "=r"(b1) : "r"(a));
}
__device__ __forceinline__ void mbar_init(u32 mbar, u32 cnt) {
    asm volatile("mbarrier.init.shared.b64 [%0], %1;" :: "r"(mbar), "r"(cnt) : "memory");
}
__device__ __forceinline__ void mbar_expect_tx(u32 mbar, u32 bytes) {
    asm volatile("mbarrier.arrive.expect_tx.shared.b64 _, [%0], %1;"
                 :: "r"(mbar), "r"(bytes) : "memory");
}
__device__ __forceinline__ void mbar_wait(u32 mbar, u32 phase) {
    asm volatile(
        "{\n\t.reg .pred P1;\n\t"
        "WAIT_LOOP_%=:\n\t"
        "mbarrier.try_wait.parity.acquire.cta.shared::cta.b64 P1, [%0], %1, 0x989680;\n\t"
        "@P1 bra.uni WAIT_DONE_%=;\n\t"
        "bra.uni WAIT_LOOP_%=;\n\t"
        "WAIT_DONE_%=:\n\t}"
        :: "r"(mbar), "r"(phase) : "memory");
}
__device__ __forceinline__ void tma_bulk(u32 dst, const bf16* src, u32 bytes, u32 mbar) {
    asm volatile(
        "cp.async.bulk.shared::cluster.global.mbarrier::complete_tx::bytes [%0], [%1], %2, [%3];"
        :: "r"(dst), "l"(src), "r"(bytes), "r"(mbar) : "memory");
}

struct EdgeDesc { int parent; int child; int w; int act; int split; };
struct LevelDesc { EdgeDesc e[3]; };

// ---------------------------------------------------------------------------
// Wide pipeline (512 thr, S=3). Stage 64KB: [Ahi 16K | Alo 16K | Bhi 16K | Blo 16K].
// A: 64 x 128 per chunk, pitch 256B, tile-swizzled (row&7). B: FOUR 4KB tiles.
// Warps: mw = warp&3 -> m rows [16mw,16mw+16); ng = warp>>2 in 0..3 -> B tile ng.
// Inner loop per warp identical to round 11. acc[jj][t]: n-block jj of warp's
// tile, split term t.
// Invariant: committed = ch+2 entering iter ch; issue(ch+2) -> stage (ch+2)%3
// which held chunk ch-1, freed by the top barrier.
// ---------------------------------------------------------------------------
template <class FISSUE>
__device__ __forceinline__ void run_pipeL(
    char* smem, FISSUE issue, float (&acc)[2][3][4])
{
    constexpr int AHI = 0, ALO = 16384, BHI = 32768;
    constexpr int SS = 65536;
    constexpr u32 TXB = 65536;

    const int tid = threadIdx.x;
    const u32 sbase = (u32)__cvta_generic_to_shared(smem);
    const u32 mbar0 = sbase + (u32)(3 * SS);

    if (tid == 0)
#pragma unroll
        for (int s = 0; s < 3; s++) mbar_init(mbar0 + s * 8, 1);
    __syncthreads();
    if (tid == 0)
#pragma unroll
        for (int c = 0; c < 2; c++) {
            mbar_expect_tx(mbar0 + c * 8, TXB);
            issue(c, sbase + c * SS, mbar0 + c * 8);
        }

    const int lane = tid & 31;
    const int w = tid >> 5;
    const int mw = w & 3, ng = w >> 2;
    const int qq = lane >> 3, rr = lane & 7;
    const int arow = 16 * mw + ((qq & 1) ? 8 : 0) + rr;
    const int aks = (qq >> 1) & 1;
    const u32 abase = (u32)(arow * 256);
    const int axor = arow & 7;
    const int bks = qq & 1;
    const u32 b0base = (u32)(ng * 4096 + rr * 256);
    const u32 b1base = (u32)(ng * 4096 + (8 + rr) * 256);
    const int bxor = rr;

    for (int ch = 0; ch < NCHUNK; ++ch) {
        __syncthreads();   // stage (ch-1)%3 free -> refill allowed
        const int sw = (ch + 2) % 3;
        if (tid == 0 && ch + 2 < NCHUNK) {
            mbar_expect_tx(mbar0 + sw * 8, TXB);
            issue(ch + 2, sbase + sw * SS, mbar0 + sw * 8);
        }
        const int sc = ch % 3;
        mbar_wait(mbar0 + sc * 8, (ch / 3) & 1);
        const u32 st = sbase + (u32)(sc * SS);
#pragma unroll
        for (int k16 = 0; k16 < KC / 16; k16++) {
            const int aslot = (k16 << 1) | aks;
            const u32 aoff = (u32)((aslot ^ axor) << 4);
            u32 ah[4], al[4];
            ldmA(st + AHI + abase + aoff, ah);
            ldmA(st + ALO + abase + aoff, al);
            const u32 boff = (u32)((((k16 << 1) | bks) ^ bxor) << 4);
            u32 bh0, bh1, bl0, bl1;
            ldmB(st + BHI + b0base + boff, bh0, bh1);
            ldmB(st + BHI + 16384 + b0base + boff, bl0, bl1);
            mma16816(acc[0][0], ah, bh0, bh1);
            mma16816(acc[0][1], ah, bl0, bl1);
            mma16816(acc[0][2], al, bh0, bh1);
            ldmB(st + BHI + b1base + boff, bh0, bh1);
            ldmB(st + BHI + 16384 + b1base + boff, bl0, bl1);
            mma16816(acc[1][0], ah, bh0, bh1);
            mma16816(acc[1][1], ah, bl0, bl1);
            mma16816(acc[1][2], al, bh0, bh1);
        }
    }
    __syncthreads();   // stages dead; smem reusable for epilogue exchange
}

// ---------------------------------------------------------------------------
// Precomp pipeline — verbatim round 11 (256 thr, S=4, 2 B tiles, linear A).
// ---------------------------------------------------------------------------
template <class FISSUE>
__device__ __forceinline__ void run_pipeP(
    char* smem, FISSUE issue, float (&acc)[2][3][4])
{
    constexpr int AHI = 0, ALO = 16384, BHI = 32768, BLO = 40960;
    constexpr int SS = 49152;
    constexpr u32 TXB = 49152;

    const int tid = threadIdx.x;
    const u32 sbase = (u32)__cvta_generic_to_shared(smem);
    const u32 mbar0 = sbase + (u32)(4 * SS);

    if (tid == 0)
#pragma unroll
        for (int s = 0; s < 4; s++) mbar_init(mbar0 + s * 8, 1);
    __syncthreads();
    if (tid == 0)
#pragma unroll
        for (int c = 0; c < 3; c++) {
            mbar_expect_tx(mbar0 + c * 8, TXB);
            issue(c, sbase + c * SS, mbar0 + c * 8);
        }

    const int lane = tid & 31;
    const int mw = (tid >> 5) & 3, ng = tid >> 7;
    const int qq = lane >> 3, rr = lane & 7;
    const int arow = 16 * mw + ((qq & 1) ? 8 : 0) + rr;
    const int aks = (qq >> 1) & 1;
    const u32 abase = (u32)(arow * 256);
    const int bks = qq & 1;
    const u32 b0base = (u32)(ng * 4096 + rr * 256);
    const u32 b1base = (u32)(ng * 4096 + (8 + rr) * 256);
    const int bxor = rr;

    for (int ch = 0; ch < NCHUNK; ++ch) {
        __syncthreads();
        if (tid == 0 && ch + 3 < NCHUNK) {
            const int s = (ch + 3) & 3;
            mbar_expect_tx(mbar0 + s * 8, TXB);
            issue(ch + 3, sbase + s * SS, mbar0 + s * 8);
        }
        mbar_wait(mbar0 + (ch & 3) * 8, (ch >> 2) & 1);
        const u32 st = sbase + (u32)((ch & 3) * SS);
#pragma unroll
        for (int k16 = 0; k16 < KC / 16; k16++) {
            const u32 aoff = (u32)(((k16 << 1) | aks) << 4);   // linear A
            u32 ah[4], al[4];
            ldmA(st + AHI + abase + aoff, ah);
            ldmA(st + ALO + abase + aoff, al);
            const u32 boff = (u32)((((k16 << 1) | bks) ^ bxor) << 4);
            u32 bh0, bh1, bl0, bl1;
            ldmB(st + BHI + b0base + boff, bh0, bh1);
            ldmB(st + BLO + b0base + boff, bl0, bl1);
            mma16816(acc[0][0], ah, bh0, bh1);
            mma16816(acc[0][1], ah, bl0, bl1);
            mma16816(acc[0][2], al, bh0, bh1);
            ldmB(st + BHI + b1base + boff, bh0, bh1);
            ldmB(st + BLO + b1base + boff, bl0, bl1);
            mma16816(acc[1][0], ah, bh0, bh1);
            mma16816(acc[1][1], ah, bl0, bl1);
            mma16816(acc[1][2], al, bh0, bh1);
        }
    }
    __syncthreads();
}

constexpr int SMEM_T = 196608 + 64;   // 196672, both pipelines

#define ASUM(jj, i) (acc[jj][0][i] + acc[jj][1][i] + acc[jj][2][i])

// ---------------------------------------------------------------------------
// prep: split fp32 operands into bf16 hi/lo.
// ---------------------------------------------------------------------------
constexpr int U_W = 11000 * 250;
constexpr int U_DEC = 10000 * 250;
constexpr int U_EMB = 10000 * 250;
constexpr int U_HID = 64 * 250;
constexpr int U_WX = 1000 * 250;
constexpr int P0 = U_W;
constexpr int P1 = P0 + U_W;
constexpr int P2 = P1 + U_DEC;
constexpr int P3 = P2 + U_EMB;
constexpr int P4 = P3 + U_HID;
constexpr int P5 = P4 + U_WX;
constexpr int P6 = P5 + U_WX;
constexpr int PREP_UNITS = P6;

__device__ __forceinline__ void split4_store(float4 v, bf16* hi, bf16* lo, size_t o) {
    bf16 h0, l0, h1, l1, h2, l2, h3, l3;
    split1(v.x, h0, l0); split1(v.y, h1, l1); split1(v.z, h2, l2); split1(v.w, h3, l3);
    *(uint2*)&hi[o] = make_uint2(b2u(h0, h1), b2u(h2, h3));
    *(uint2*)&lo[o] = make_uint2(b2u(l0, l1), b2u(l2, l3));
}

__global__ __launch_bounds__(256) void prep_split(
    const float* __restrict__ Wh, const float* __restrict__ Wc,
    const float* __restrict__ dec_w, const float* __restrict__ emb,
    const float* __restrict__ hidden,
    const float* __restrict__ w_xh, const float* __restrict__ w_xc)
{
    int i = blockIdx.x * 256 + threadIdx.x;
    if (i >= PREP_UNITS) return;
    if (i < P0) {
        int row = i / 250, k = (i % 250) * 4;
        int e = row / 1000, n = row % 1000;
        split4_store(*(const float4*)(Wh + (size_t)row * 1000 + k),
                     g_Whhi + (size_t)e * TILEMAT, g_Whlo + (size_t)e * TILEMAT,
                     tile_off(n, k));
    } else if (i < P1) {
        int j = i - P0; int row = j / 250, k = (j % 250) * 4;
        int e = row / 1000, n = row % 1000;
        split4_store(*(const float4*)(Wc + (size_t)row * 1000 + k),
                     g_Wchi + (size_t)e * TILEMAT, g_Wclo + (size_t)e * TILEMAT,
                     tile_off(n, k));
    } else if (i < P2) {
        int j = i - P1; int row = j / 250, k = (j % 250) * 4;
        split4_store(*(const float4*)(dec_w + (size_t)row * 1000 + k),
                     g_dect_hi, g_dect_lo, tile_off(row, k));
    } else if (i < P3) {
        int j = i - P2; int row = j / 250, k = (j % 250) * 4;
        split4_store(*(const float4*)(emb + (size_t)row * 1000 + k),
                     g_embhi, g_emblo, (size_t)row * KP + k);
    } else if (i < P4) {
        int j = i - P3; int row = j / 250, k = (j % 250) * 4;
        split4_store(*(const float4*)(hidden + (size_t)row * 1000 + k),
                     g_hhi[11], g_hlo[11], chmaj_off(row, k));
    } else if (i < P5) {
        int j = i - P4; int row = j / 250, k = (j % 250) * 4;
        split4_store(*(const float4*)(w_xh + (size_t)row * 2000 + k),
                     g_wxhe_hi, g_wxhe_lo, tile_off(row, k));
        split4_store(*(const float4*)(w_xh + (size_t)row * 2000 + 1000 + k),
                     g_wxhh_hi, g_wxhh_lo, tile_off(row, k));
    } else {
        int j = i - P5; int row = j / 250, k = (j % 250) * 4;
        split4_store(*(const float4*)(w_xc + (size_t)row * 2000 + k),
                     g_wxce_hi, g_wxce_lo, tile_off(row, k));
        split4_store(*(const float4*)(w_xc + (size_t)row * 2000 + 1000 + k),
                     g_wxch_hi, g_wxch_lo, tile_off(row, k));
    }
}

// ---------------------------------------------------------------------------
// precomp: P{h,c} = gather(emb) @ w_x{h,c}_embpart^T + bias. grid (63, 64),
// 256 threads, round-11 pipeline.
// ---------------------------------------------------------------------------
__global__ __launch_bounds__(256) void precomp_mma(
    const int* __restrict__ inputs,
    const float* __restrict__ b_xh, const float* __restrict__ b_xc)
{
    extern __shared__ char smem[];
    __shared__ int toks[64];
    const int m0 = blockIdx.y * 64;
    if (threadIdx.x < 64) toks[threadIdx.x] = inputs[m0 + threadIdx.x];

    const int nblk = blockIdx.x;
    const int n0 = nblk * 16;
    float acc[2][3][4] = {};
    run_pipeP(smem,
        [&](int ch, u32 st, u32 mb) {
            const int k0 = ch * KC;
            for (int r = 0; r < 64; r++) {
                size_t so = (size_t)toks[r] * KP + k0;
                tma_bulk(st + r * 256,         g_embhi + so, 256, mb);
                tma_bulk(st + 16384 + r * 256, g_emblo + so, 256, mb);
            }
            size_t to = ((size_t)nblk * 8 + ch) * 2048;
            tma_bulk(st + 32768,        g_wxhe_hi + to, 4096, mb);
            tma_bulk(st + 32768 + 4096, g_wxce_hi + to, 4096, mb);
            tma_bulk(st + 40960,        g_wxhe_lo + to, 4096, mb);
            tma_bulk(st + 40960 + 4096, g_wxce_lo + to, 4096, mb);
        }, acc);

    const int lane = threadIdx.x & 31;
    const int mw = (threadIdx.x >> 5) & 3, ng = threadIdx.x >> 7;
    const int g = lane >> 2, tq = lane & 3;
    const float* bias = ng ? b_xc : b_xh;
    float* dst = ng ? g_Pc : g_Ph;
#pragma unroll
    for (int jj = 0; jj < 2; jj++)
#pragma unroll
        for (int r = 0; r < 2; r++) {
            const int m = m0 + 16 * mw + g + 8 * r;
            const int n = n0 + jj * 8 + 2 * tq;
            if (n < Hd) {
                float2 bb = *(const float2*)&bias[n];
                *(float2*)&dst[(size_t)m * Hd + n] =
                    make_float2(ASUM(jj, 2 * r) + bb.x, ASUM(jj, 2 * r + 1) + bb.y);
            }
        }
}

// ---------------------------------------------------------------------------
// cell0: dual GEMM vs h_prev + precomputed emb part. grid 32, 512 threads.
// B tiles: [wxhh nb0 | wxch nb0 | wxhh nb1 | wxch nb1].
// ---------------------------------------------------------------------------
__global__ __launch_bounds__(512) void cell0_mma(const float* __restrict__ hidden, int t)
{
    extern __shared__ char smem[];
    const float* __restrict__ hprev = (t == 0) ? hidden : g_h[11];
    const int nblk = blockIdx.x;
    float acc[2][3][4] = {};
    run_pipeL(smem,
        [&](int ch, u32 st, u32 mb) {
            tma_bulk(st,         g_hhi[11] + ch * 8192, 16384, mb);
            tma_bulk(st + 16384, g_hlo[11] + ch * 8192, 16384, mb);
            size_t t0 = ((size_t)(nblk * 2) * 8 + ch) * 2048;
            size_t t1 = ((size_t)(nblk * 2 + 1) * 8 + ch) * 2048;
            tma_bulk(st + 32768,         g_wxhh_hi + t0, 4096, mb);
            tma_bulk(st + 32768 + 4096,  g_wxch_hi + t0, 4096, mb);
            tma_bulk(st + 32768 + 8192,  g_wxhh_hi + t1, 4096, mb);
            tma_bulk(st + 32768 + 12288, g_wxch_hi + t1, 4096, mb);
            tma_bulk(st + 49152,         g_wxhh_lo + t0, 4096, mb);
            tma_bulk(st + 49152 + 4096,  g_wxch_lo + t0, 4096, mb);
            tma_bulk(st + 49152 + 8192,  g_wxhh_lo + t1, 4096, mb);
            tma_bulk(st + 49152 + 12288, g_wxch_lo + t1, 4096, mb);
        }, acc);

    float* ex = (float*)smem;   // [2 nb][64 m][16 n]
    const int lane = threadIdx.x & 31;
    const int w = threadIdx.x >> 5;
    const int mw = w & 3, ng = w >> 2;
    const int g = lane >> 2, tq = lane & 3;
    const int nbi = ng >> 1;                    // which of the CTA's 2 n-tiles
    const int n0w = (nblk * 2 + nbi) * 16;
    if (ng & 1) {                               // wxch (c0) warps -> exchange
#pragma unroll
        for (int jj = 0; jj < 2; jj++)
#pragma unroll
            for (int r = 0; r < 2; r++)
                *(float2*)&ex[nbi * 1024 + (16 * mw + g + 8 * r) * 16 + jj * 8 + 2 * tq] =
                    make_float2(ASUM(jj, 2 * r), ASUM(jj, 2 * r + 1));
    }
    __syncthreads();
    if (!(ng & 1)) {
#pragma unroll
        for (int jj = 0; jj < 2; jj++)
#pragma unroll
            for (int r = 0; r < 2; r++) {
                const int m = 16 * mw + g + 8 * r;
                const int n = n0w + jj * 8 + 2 * tq;
                if (n < Hd) {
                    const int idx = m * Hd + n;
                    const size_t pidx = (size_t)(t * Bb + m) * Hd + n;
                    float2 sc = *(const float2*)&ex[nbi * 1024 + (16 * mw + g + 8 * r) * 16 + jj * 8 + 2 * tq];
                    float2 ph = *(const float2*)&g_Ph[pidx];
                    float2 pc = *(const float2*)&g_Pc[pidx];
                    float2 hp = *(const float2*)&hprev[idx];
                    float c0a = sigmf(sc.x + pc.x);
                    float c0b = sigmf(sc.y + pc.y);
                    float h0a = c0a * tanhf(ASUM(jj, 2 * r) + ph.x) + (1.0f - c0a) * hp.x;
                    float h0b = c0b * tanhf(ASUM(jj, 2 * r + 1) + ph.y) + (1.0f - c0b) * hp.y;
                    *(float2*)&g_c0[idx] = make_float2(c0a, c0b);
                    *(float2*)&g_h[0][idx] = make_float2(h0a, h0b);
                    bf16 ha, la, hb, lb;
                    split1(h0a, ha, la); split1(h0b, hb, lb);
                    const size_t so = chmaj_off(m, n);
                    *(u32*)&g_hhi[0][so] = b2u(ha, hb);
                    *(u32*)&g_hlo[0][so] = b2u(la, lb);
                }
            }
    }
}

// ---------------------------------------------------------------------------
// Generic DAG level. grid = (32, n_edges), 512 threads.
// B tiles: [Wh nb0 | Wc nb0 | Wh nb1 | Wc nb1].
// ---------------------------------------------------------------------------
__global__ __launch_bounds__(512) void level_mma(LevelDesc L)
{
    extern __shared__ char smem[];
    const EdgeDesc ed = L.e[blockIdx.y];
    const float* __restrict__ hin = g_h[ed.parent];
    float* __restrict__ hout = g_h[ed.child];
    const bf16* ahi = g_hhi[ed.parent];
    const bf16* alo = g_hlo[ed.parent];
    const size_t wb = (size_t)ed.w * TILEMAT;
    const int nblk = blockIdx.x;

    float acc[2][3][4] = {};
    run_pipeL(smem,
        [&](int ch, u32 st, u32 mb) {
            tma_bulk(st,         ahi + ch * 8192, 16384, mb);
            tma_bulk(st + 16384, alo + ch * 8192, 16384, mb);
            size_t t0 = wb + ((size_t)(nblk * 2) * 8 + ch) * 2048;
            size_t t1 = wb + ((size_t)(nblk * 2 + 1) * 8 + ch) * 2048;
            tma_bulk(st + 32768,         g_Whhi + t0, 4096, mb);
            tma_bulk(st + 32768 + 4096,  g_Wchi + t0, 4096, mb);
            tma_bulk(st + 32768 + 8192,  g_Whhi + t1, 4096, mb);
            tma_bulk(st + 32768 + 12288, g_Wchi + t1, 4096, mb);
            tma_bulk(st + 49152,         g_Whlo + t0, 4096, mb);
            tma_bulk(st + 49152 + 4096,  g_Wclo + t0, 4096, mb);
            tma_bulk(st + 49152 + 8192,  g_Whlo + t1, 4096, mb);
            tma_bulk(st + 49152 + 12288, g_Wclo + t1, 4096, mb);
        }, acc);

    float* ex = (float*)smem;
    const int lane = threadIdx.x & 31;
    const int w = threadIdx.x >> 5;
    const int mw = w & 3, ng = w >> 2;
    const int g = lane >> 2, tq = lane & 3;
    const int nbi = ng >> 1;
    const int n0w = (nblk * 2 + nbi) * 16;
    if (ng & 1) {                               // Wc warps -> exchange
#pragma unroll
        for (int jj = 0; jj < 2; jj++)
#pragma unroll
            for (int r = 0; r < 2; r++)
                *(float2*)&ex[nbi * 1024 + (16 * mw + g + 8 * r) * 16 + jj * 8 + 2 * tq] =
                    make_float2(ASUM(jj, 2 * r), ASUM(jj, 2 * r + 1));
    }
    __syncthreads();
    if (!(ng & 1)) {
#pragma unroll
        for (int jj = 0; jj < 2; jj++)
#pragma unroll
            for (int r = 0; r < 2; r++) {
                const int m = 16 * mw + g + 8 * r;
                const int n = n0w + jj * 8 + 2 * tq;
                if (n < Hd) {
                    const int idx = m * Hd + n;
                    float2 sc = *(const float2*)&ex[nbi * 1024 + (16 * mw + g + 8 * r) * 16 + jj * 8 + 2 * tq];
                    float2 hi2 = *(const float2*)&hin[idx];
                    float2 c02 = *(const float2*)&g_c0[idx];
                    float oa = sigmf(sc.x) * applyAct(ed.act, ASUM(jj, 2 * r))
                               + (1.0f - c02.x) * hi2.x;
                    float ob = sigmf(sc.y) * applyAct(ed.act, ASUM(jj, 2 * r + 1))
                               + (1.0f - c02.y) * hi2.y;
                    *(float2*)&hout[idx] = make_float2(oa, ob);
                    if (ed.split) {
                        bf16 ha, la, hb, lb;
                        split1(oa, ha, la); split1(ob, hb, lb);
                        const size_t so = chmaj_off(m, n);
                        *(u32*)&g_hhi[ed.child][so] = b2u(ha, hb);
                        *(u32*)&g_hlo[ed.child][so] = b2u(la, lb);
                    }
                }
            }
    }
}

// ---------------------------------------------------------------------------
// Leaf mean: out[t] = (h5+h7+h8+h9+h10+h11)/6 -> chunk-major split outs.
// ---------------------------------------------------------------------------
__global__ __launch_bounds__(256) void mean_kernel(int t)
{
    int i = blockIdx.x * 256 + threadIdx.x;
    if (i < Bb * Hd / 2) {
        int idx = 2 * i;
        int m = idx / Hd, n = idx % Hd;
        float s0 = (g_h[5][idx] + g_h[7][idx] + g_h[8][idx] + g_h[9][idx]
                    + g_h[10][idx] + g_h[11][idx]) * (1.0f / 6.0f);
        float s1 = (g_h[5][idx + 1] + g_h[7][idx + 1] + g_h[8][idx + 1] + g_h[9][idx + 1]
                    + g_h[10][idx + 1] + g_h[11][idx + 1]) * (1.0f / 6.0f);
        bf16 h0, l0, h1, l1;
        split1(s0, h0, l0); split1(s1, h1, l1);
        size_t o = (size_t)t * HCH + chmaj_off(m, n);
        *(u32*)&g_outshi[o] = b2u(h0, h1);
        *(u32*)&g_outslo[o] = b2u(l0, l1);
    }
}

// ---------------------------------------------------------------------------
// Decoder: out[m][v] = outs[m] . dec_w[v] + dec_b[v]; grid (157, 64), 512 thr.
// B tiles: 4 consecutive dec tiles; warp ng owns tile nblk*4+ng (16 cols).
// ---------------------------------------------------------------------------
__global__ __launch_bounds__(512) void decoder_mma(
    const float* __restrict__ dec_b, float* __restrict__ out)
{
    extern __shared__ char smem[];
    const int t = blockIdx.y;
    const int nblk = blockIdx.x;
    const bf16* ahi = g_outshi + (size_t)t * HCH;
    const bf16* alo = g_outslo + (size_t)t * HCH;

    float acc[2][3][4] = {};
    run_pipeL(smem,
        [&](int ch, u32 st, u32 mb) {
            tma_bulk(st,         ahi + ch * 8192, 16384, mb);
            tma_bulk(st + 16384, alo + ch * 8192, 16384, mb);
#pragma unroll
            for (int q = 0; q < 4; q++) {
                size_t to = ((size_t)(nblk * 4 + q) * 8 + ch) * 2048;
                tma_bulk(st + 32768 + q * 4096, g_dect_hi + to, 4096, mb);
                tma_bulk(st + 49152 + q * 4096, g_dect_lo + to, 4096, mb);
            }
        }, acc);

    const int lane = threadIdx.x & 31;
    const int w = threadIdx.x >> 5;
    const int mw = w & 3, ng = w >> 2;
    const int g = lane >> 2, tq = lane & 3;
    const int m0 = t * 64;
    const int n0w = (nblk * 4 + ng) * 16;
#pragma unroll
    for (int jj = 0; jj < 2; jj++)
#pragma unroll
        for (int r = 0; r < 2; r++) {
            const int m = m0 + 16 * mw + g + 8 * r;
            const int n = n0w + jj * 8 + 2 * tq;
            if (n < Vv) {
                float2 db = *(const float2*)&dec_b[n];
                *(float2*)&out[(size_t)m * Vv + n] =
                    make_float2(ASUM(jj, 2 * r) + db.x, ASUM(jj, 2 * r + 1) + db.y);
            }
        }
}

} // namespace

// ---------------------------------------------------------------------------
extern "C" void kernel_launch(void* const* d_in, const int* in_sizes, int n_in,
                              void* d_out, int out_size)
{
    (void)in_sizes; (void)n_in; (void)out_size;

    const int*   inputs = (const int*)  d_in[0];
    const float* hidden = (const float*)d_in[1];
    const float* emb    = (const float*)d_in[2];
    const float* w_xh   = (const float*)d_in[3];
    const float* b_xh   = (const float*)d_in[4];
    const float* w_xc   = (const float*)d_in[5];
    const float* b_xc   = (const float*)d_in[6];
    const float* Wh     = (const float*)d_in[7];
    const float* Wc     = (const float*)d_in[8];
    const float* dec_w  = (const float*)d_in[9];
    const float* dec_b  = (const float*)d_in[10];
    float* out = (float*)d_out;

    cudaFuncSetAttribute(precomp_mma, cudaFuncAttributeMaxDynamicSharedMemorySize, SMEM_T);
    cudaFuncSetAttribute(cell0_mma,   cudaFuncAttributeMaxDynamicSharedMemorySize, SMEM_T);
    cudaFuncSetAttribute(level_mma,   cudaFuncAttributeMaxDynamicSharedMemorySize, SMEM_T);
    cudaFuncSetAttribute(decoder_mma, cudaFuncAttributeMaxDynamicSharedMemorySize, SMEM_T);

    // acts: 0=relu, 1=tanh, 2=sigmoid, 3=identity; split=1 if child is a parent
    const LevelDesc LV1 = {{ {0, 1, 0, 0, 1},  {0, 6, 1, 1, 1},  {0, 0, 0, 3, 0} }};
    const LevelDesc LV2 = {{ {1, 2, 2, 0, 1},  {1, 8, 3, 2, 0},  {6, 7, 10, 1, 0} }};
    const LevelDesc LV3 = {{ {2, 3, 4, 1, 1},  {2, 9, 5, 0, 0},  {0, 0, 0, 3, 0} }};
    const LevelDesc LV4 = {{ {3, 4, 6, 3, 1},  {3, 10, 7, 1, 0}, {0, 0, 0, 3, 0} }};
    const LevelDesc LV5 = {{ {4, 5, 8, 0, 0},  {4, 11, 9, 2, 1}, {0, 0, 0, 3, 0} }};

    prep_split<<<(PREP_UNITS + 255) / 256, 256>>>(Wh, Wc, dec_w, emb, hidden, w_xh, w_xc);
    precomp_mma<<<dim3(63, 64), 256, SMEM_T>>>(inputs, b_xh, b_xc);

    for (int t = 0; t < Tt; ++t) {
        cell0_mma<<<32, 512, SMEM_T>>>(hidden, t);
        level_mma<<<dim3(32, 2), 512, SMEM_T>>>(LV1);
        level_mma<<<dim3(32, 3), 512, SMEM_T>>>(LV2);
        level_mma<<<dim3(32, 2), 512, SMEM_T>>>(LV3);
        level_mma<<<dim3(32, 2), 512, SMEM_T>>>(LV4);
        level_mma<<<dim3(32, 2), 512, SMEM_T>>>(LV5);
        mean_kernel<<<(Bb * Hd / 2 + 255) / 256, 256>>>(t);
    }

    decoder_mma<<<dim3(157, 64), 512, SMEM_T>>>(dec_b, out);
}

// round 17
// speedup vs baseline: 1.1616x; 1.1616x over previous
#include <cuda_runtime.h>
#include <cuda_bf16.h>

// ---------------------------------------------------------------------------
// ENAS RNN — round 17: round-11 champion kernel (TMA bulk pipeline, bf16
// 3-term split) + leaf-mean fused into the NEXT step's cell0 epilogue
// (h11(t-1) is already loaded there; other leaves are stable). One tail
// mean launch covers t = 63. Everything else byte-identical to round 11.
// ---------------------------------------------------------------------------

namespace {

typedef unsigned int u32;
typedef __nv_bfloat16 bf16;

constexpr int Hd = 1000;
constexpr int Bb = 64;
constexpr int Tt = 64;
constexpr int Vv = 10000;

constexpr int KP = 1024;            // padded K (8 chunks of 128)
constexpr int KC = 128;
constexpr int NCHUNK = 8;
constexpr int TILEMAT = 63 * 8 * 2048;   // one 1000x1000 matrix in 16x128 tiles
constexpr int DECT = 626 * 8 * 2048;     // decoder tiles (626 nblks, last zero)
constexpr int HCH = 8 * 64 * 128;        // chunk-major h slab = 65536 elems

// ---------------- static device storage (zero-init = implicit padding) -----
__device__ __align__(1024) bf16 g_Whhi[11 * TILEMAT], g_Whlo[11 * TILEMAT];
__device__ __align__(1024) bf16 g_Wchi[11 * TILEMAT], g_Wclo[11 * TILEMAT];
__device__ __align__(1024) bf16 g_dect_hi[DECT], g_dect_lo[DECT];
__device__ __align__(1024) bf16 g_embhi[10000 * KP], g_emblo[10000 * KP];
__device__ __align__(1024) bf16 g_wxhe_hi[TILEMAT], g_wxhe_lo[TILEMAT];
__device__ __align__(1024) bf16 g_wxhh_hi[TILEMAT], g_wxhh_lo[TILEMAT];
__device__ __align__(1024) bf16 g_wxce_hi[TILEMAT], g_wxce_lo[TILEMAT];
__device__ __align__(1024) bf16 g_wxch_hi[TILEMAT], g_wxch_lo[TILEMAT];

__device__ __align__(1024) float g_h[12][Bb * Hd];
__device__ __align__(1024) bf16  g_hhi[12][HCH], g_hlo[12][HCH];  // chunk-major, swizzled
__device__ __align__(1024) float g_c0[Bb * Hd];
__device__ __align__(1024) float g_Ph[Tt * Bb * Hd], g_Pc[Tt * Bb * Hd];
__device__ __align__(1024) bf16  g_outshi[Tt * HCH], g_outslo[Tt * HCH];

// ---------------- helpers ---------------------------------------------------
__device__ __forceinline__ float sigmf(float x) { return 1.0f / (1.0f + expf(-x)); }

__device__ __forceinline__ float applyAct(int a, float v) {
    switch (a) {
        case 0: return fmaxf(v, 0.0f);
        case 1: return tanhf(v);
        case 2: return sigmf(v);
        default: return v;
    }
}

__device__ __forceinline__ void split1(float x, bf16& h, bf16& l) {
    h = __float2bfloat16(x);
    l = __float2bfloat16(x - __bfloat162float(h));
}
__device__ __forceinline__ u32 b2u(bf16 a, bf16 b) {
    return (u32)__bfloat16_as_ushort(a) | ((u32)__bfloat16_as_ushort(b) << 16);
}

// tile layout: matrix [rows][k<=1024] as [nblk][chunk][16 rows][128 k],
// 16B slots XOR-swizzled by (row&7) for conflict-free ldmatrix.
__device__ __forceinline__ size_t tile_off(int n, int k) {
    int within = n & 15;
    int slot = (k >> 3) & 15;
    return ((size_t)((n >> 4) * 8 + (k >> 7))) * 2048
           + within * 128 + (size_t)((slot ^ (within & 7)) << 3) + (k & 7);
}
// chunk-major swizzled A slab: [chunk][64 m][128 k]
__device__ __forceinline__ size_t chmaj_off(int m, int n) {
    int slot = ((n >> 3) & 15) ^ (m & 7);
    return ((size_t)(n >> 7) * 64 + m) * 128 + slot * 8 + (n & 7);
}

__device__ __forceinline__ void mma16816(float (&d)[4], const u32 (&a)[4], u32 b0, u32 b1) {
    asm volatile(
        "mma.sync.aligned.m16n8k16.row.col.f32.bf16.bf16.f32 "
        "{%0,%1,%2,%3}, {%4,%5,%6,%7}, {%8,%9}, {%0,%1,%2,%3};"
        : "+f"(d[0]), "+f"(d[1]), "+f"(d[2]), "+f"(d[3])
        : "r"(a[0]), "r"(a[1]), "r"(a[2]), "r"(a[3]), "r"(b0), "r"(b1));
}
__device__ __forceinline__ void ldmA(u32 a, u32 (&r)[4]) {
    asm volatile("ldmatrix.sync.aligned.m8n8.x4.shared.b16 {%0,%1,%2,%3}, [%4];"
                 : "=r"(r[0]), "=r"(r[1]), "=r"(r[2]), "=r"(r[3]) : "r"(a));
}
__device__ __forceinline__ void ldmB(u32 a, u32& b0, u32& b1) {
    asm volatile("ldmatrix.sync.aligned.m8n8.x2.shared.b16 {%0,%1}, [%2];"
                 : "=r"(b0), "=r"(b1) : "r"(a));
}
__device__ __forceinline__ void mbar_init(u32 mbar, u32 cnt) {
    asm volatile("mbarrier.init.shared.b64 [%0], %1;" :: "r"(mbar), "r"(cnt) : "memory");
}
__device__ __forceinline__ void mbar_expect_tx(u32 mbar, u32 bytes) {
    asm volatile("mbarrier.arrive.expect_tx.shared.b64 _, [%0], %1;"
                 :: "r"(mbar), "r"(bytes) : "memory");
}
__device__ __forceinline__ void mbar_wait(u32 mbar, u32 phase) {
    asm volatile(
        "{\n\t.reg .pred P1;\n\t"
        "WAIT_LOOP_%=:\n\t"
        "mbarrier.try_wait.parity.acquire.cta.shared::cta.b64 P1, [%0], %1, 0x989680;\n\t"
        "@P1 bra.uni WAIT_DONE_%=;\n\t"
        "bra.uni WAIT_LOOP_%=;\n\t"
        "WAIT_DONE_%=:\n\t}"
        :: "r"(mbar), "r"(phase) : "memory");
}
__device__ __forceinline__ void tma_bulk(u32 dst, const bf16* src, u32 bytes, u32 mbar) {
    asm volatile(
        "cp.async.bulk.shared::cluster.global.mbarrier::complete_tx::bytes [%0], [%1], %2, [%3];"
        :: "r"(dst), "l"(src), "r"(bytes), "r"(mbar) : "memory");
}

struct EdgeDesc { int parent; int child; int w; int act; int split; };
struct LevelDesc { EdgeDesc e[3]; };

// ---------------------------------------------------------------------------
// TMA-fed pipeline (round-11). A: 64 x 1024, pitch 256B; SWIZA 1 = tile-
// swizzled A rows, 0 = linear. B: two 4KB tiles per chunk (hi+lo).
// 256 thr = 8 warps: mw = warp&3 -> m rows; ng = warp>>2 -> B tile ng.
// ---------------------------------------------------------------------------
template <int SWIZA, class FISSUE>
__device__ __forceinline__ void run_tma_pipeline(
    char* smem, FISSUE issue, float (&acc)[2][3][4])
{
    constexpr int AHI = 0;
    constexpr int ALO = 16384;
    constexpr int BHI = 32768;
    constexpr int SS  = 49152;
    constexpr u32 TXB = 49152;

    const int tid = threadIdx.x;
    const u32 sbase = (u32)__cvta_generic_to_shared(smem);
    const u32 mbar0 = sbase + (u32)(4 * SS);

    if (tid == 0)
#pragma unroll
        for (int s = 0; s < 4; s++) mbar_init(mbar0 + s * 8, 1);
    __syncthreads();
    if (tid == 0)
#pragma unroll
        for (int c = 0; c < 3; c++) {
            mbar_expect_tx(mbar0 + c * 8, TXB);
            issue(c, sbase + c * SS, mbar0 + c * 8);
        }

    const int lane = tid & 31;
    const int mw = (tid >> 5) & 3, ng = tid >> 7;
    const int qq = lane >> 3, rr = lane & 7;
    const int arow = 16 * mw + ((qq & 1) ? 8 : 0) + rr;
    const int aks = (qq >> 1) & 1;
    const u32 abase = (u32)(arow * 256);
    const int axor = SWIZA ? (arow & 7) : 0;
    const int bks = qq & 1;
    const u32 b0base = (u32)(ng * 4096 + rr * 256);
    const u32 b1base = (u32)(ng * 4096 + (8 + rr) * 256);
    const int bxor = rr;

    for (int ch = 0; ch < NCHUNK; ++ch) {
        __syncthreads();   // all warps done with stage (ch-1)&3 -> safe to refill
        if (tid == 0 && ch + 3 < NCHUNK) {
            const int s = (ch + 3) & 3;
            mbar_expect_tx(mbar0 + s * 8, TXB);
            issue(ch + 3, sbase + s * SS, mbar0 + s * 8);
        }
        mbar_wait(mbar0 + (ch & 3) * 8, (ch >> 2) & 1);
        const u32 st = sbase + (u32)((ch & 3) * SS);
#pragma unroll
        for (int k16 = 0; k16 < KC / 16; k16++) {
            const int aslot = (k16 << 1) | aks;
            const u32 aoff = (u32)((aslot ^ axor) << 4);
            u32 ah[4], al[4];
            ldmA(st + AHI + abase + aoff, ah);
            ldmA(st + ALO + abase + aoff, al);
            const u32 boff = (u32)((((k16 << 1) | bks) ^ bxor) << 4);
            u32 bh0, bh1, bl0, bl1;
            ldmB(st + BHI + b0base + boff, bh0, bh1);
            ldmB(st + BHI + 8192 + b0base + boff, bl0, bl1);
            mma16816(acc[0][0], ah, bh0, bh1);
            mma16816(acc[0][1], ah, bl0, bl1);
            mma16816(acc[0][2], al, bh0, bh1);
            ldmB(st + BHI + b1base + boff, bh0, bh1);
            ldmB(st + BHI + 8192 + b1base + boff, bl0, bl1);
            mma16816(acc[1][0], ah, bh0, bh1);
            mma16816(acc[1][1], ah, bl0, bl1);
            mma16816(acc[1][2], al, bh0, bh1);
        }
    }
    __syncthreads();   // stages dead; smem reusable for epilogue exchange
}

constexpr int SMEM_T = 49152 * 4 + 64;   // 196672

// Epilogue exchange through (dead) pipeline smem.
__device__ __forceinline__ void ex_store(float* ex, const float (&a)[2][3][4],
                                         int mw, int lane) {
    const int g = lane >> 2, tq = lane & 3;
#pragma unroll
    for (int jj = 0; jj < 2; jj++)
#pragma unroll
        for (int r = 0; r < 2; r++) {
            float2 v = make_float2(
                a[jj][0][2 * r] + a[jj][1][2 * r] + a[jj][2][2 * r],
                a[jj][0][2 * r + 1] + a[jj][1][2 * r + 1] + a[jj][2][2 * r + 1]);
            *(float2*)&ex[(16 * mw + g + 8 * r) * 16 + jj * 8 + 2 * tq] = v;
        }
}

#define ASUM(jj, i) (acc[jj][0][i] + acc[jj][1][i] + acc[jj][2][i])

// ---------------------------------------------------------------------------
// prep: split fp32 operands into bf16 hi/lo.
// ---------------------------------------------------------------------------
constexpr int U_W = 11000 * 250;
constexpr int U_DEC = 10000 * 250;
constexpr int U_EMB = 10000 * 250;
constexpr int U_HID = 64 * 250;
constexpr int U_WX = 1000 * 250;
constexpr int P0 = U_W;
constexpr int P1 = P0 + U_W;
constexpr int P2 = P1 + U_DEC;
constexpr int P3 = P2 + U_EMB;
constexpr int P4 = P3 + U_HID;
constexpr int P5 = P4 + U_WX;
constexpr int P6 = P5 + U_WX;
constexpr int PREP_UNITS = P6;

__device__ __forceinline__ void split4_store(float4 v, bf16* hi, bf16* lo, size_t o) {
    bf16 h0, l0, h1, l1, h2, l2, h3, l3;
    split1(v.x, h0, l0); split1(v.y, h1, l1); split1(v.z, h2, l2); split1(v.w, h3, l3);
    *(uint2*)&hi[o] = make_uint2(b2u(h0, h1), b2u(h2, h3));
    *(uint2*)&lo[o] = make_uint2(b2u(l0, l1), b2u(l2, l3));
}

__global__ __launch_bounds__(256) void prep_split(
    const float* __restrict__ Wh, const float* __restrict__ Wc,
    const float* __restrict__ dec_w, const float* __restrict__ emb,
    const float* __restrict__ hidden,
    const float* __restrict__ w_xh, const float* __restrict__ w_xc)
{
    int i = blockIdx.x * 256 + threadIdx.x;
    if (i >= PREP_UNITS) return;
    if (i < P0) {
        int row = i / 250, k = (i % 250) * 4;
        int e = row / 1000, n = row % 1000;
        split4_store(*(const float4*)(Wh + (size_t)row * 1000 + k),
                     g_Whhi + (size_t)e * TILEMAT, g_Whlo + (size_t)e * TILEMAT,
                     tile_off(n, k));
    } else if (i < P1) {
        int j = i - P0; int row = j / 250, k = (j % 250) * 4;
        int e = row / 1000, n = row % 1000;
        split4_store(*(const float4*)(Wc + (size_t)row * 1000 + k),
                     g_Wchi + (size_t)e * TILEMAT, g_Wclo + (size_t)e * TILEMAT,
                     tile_off(n, k));
    } else if (i < P2) {
        int j = i - P1; int row = j / 250, k = (j % 250) * 4;
        split4_store(*(const float4*)(dec_w + (size_t)row * 1000 + k),
                     g_dect_hi, g_dect_lo, tile_off(row, k));
    } else if (i < P3) {
        int j = i - P2; int row = j / 250, k = (j % 250) * 4;
        split4_store(*(const float4*)(emb + (size_t)row * 1000 + k),
                     g_embhi, g_emblo, (size_t)row * KP + k);
    } else if (i < P4) {
        int j = i - P3; int row = j / 250, k = (j % 250) * 4;
        split4_store(*(const float4*)(hidden + (size_t)row * 1000 + k),
                     g_hhi[11], g_hlo[11], chmaj_off(row, k));
    } else if (i < P5) {
        int j = i - P4; int row = j / 250, k = (j % 250) * 4;
        split4_store(*(const float4*)(w_xh + (size_t)row * 2000 + k),
                     g_wxhe_hi, g_wxhe_lo, tile_off(row, k));
        split4_store(*(const float4*)(w_xh + (size_t)row * 2000 + 1000 + k),
                     g_wxhh_hi, g_wxhh_lo, tile_off(row, k));
    } else {
        int j = i - P5; int row = j / 250, k = (j % 250) * 4;
        split4_store(*(const float4*)(w_xc + (size_t)row * 2000 + k),
                     g_wxce_hi, g_wxce_lo, tile_off(row, k));
        split4_store(*(const float4*)(w_xc + (size_t)row * 2000 + 1000 + k),
                     g_wxch_hi, g_wxch_lo, tile_off(row, k));
    }
}

// ---------------------------------------------------------------------------
// precomp: P{h,c} = gather(emb) @ w_x{h,c}_embpart^T + bias. grid (63, 64).
// ---------------------------------------------------------------------------
__global__ __launch_bounds__(256) void precomp_mma(
    const int* __restrict__ inputs,
    const float* __restrict__ b_xh, const float* __restrict__ b_xc)
{
    extern __shared__ char smem[];
    __shared__ int toks[64];
    const int m0 = blockIdx.y * 64;
    if (threadIdx.x < 64) toks[threadIdx.x] = inputs[m0 + threadIdx.x];

    const int nblk = blockIdx.x;
    const int n0 = nblk * 16;
    float acc[2][3][4] = {};
    run_tma_pipeline<0>(smem,
        [&](int ch, u32 st, u32 mb) {
            const int k0 = ch * KC;
            for (int r = 0; r < 64; r++) {
                size_t so = (size_t)toks[r] * KP + k0;
                tma_bulk(st + r * 256,         g_embhi + so, 256, mb);
                tma_bulk(st + 16384 + r * 256, g_emblo + so, 256, mb);
            }
            size_t to = ((size_t)nblk * 8 + ch) * 2048;
            tma_bulk(st + 32768,        g_wxhe_hi + to, 4096, mb);
            tma_bulk(st + 32768 + 4096, g_wxce_hi + to, 4096, mb);
            tma_bulk(st + 40960,        g_wxhe_lo + to, 4096, mb);
            tma_bulk(st + 40960 + 4096, g_wxce_lo + to, 4096, mb);
        }, acc);

    const int lane = threadIdx.x & 31;
    const int mw = (threadIdx.x >> 5) & 3, ng = threadIdx.x >> 7;
    const int g = lane >> 2, tq = lane & 3;
    const float* bias = ng ? b_xc : b_xh;
    float* dst = ng ? g_Pc : g_Ph;
#pragma unroll
    for (int jj = 0; jj < 2; jj++)
#pragma unroll
        for (int r = 0; r < 2; r++) {
            const int m = m0 + 16 * mw + g + 8 * r;
            const int n = n0 + jj * 8 + 2 * tq;
            if (n < Hd) {
                float2 bb = *(const float2*)&bias[n];
                *(float2*)&dst[(size_t)m * Hd + n] =
                    make_float2(ASUM(jj, 2 * r) + bb.x, ASUM(jj, 2 * r + 1) + bb.y);
            }
        }
}

// ---------------------------------------------------------------------------
// cell0: dual GEMM vs h_prev + precomputed emb part. grid 63.
// FUSION (round 17): for t>0 the epilogue also emits the step-(t-1) leaf
// mean into g_outs (h11(t-1) = hp is already loaded; other leaves stable).
// ---------------------------------------------------------------------------
__global__ __launch_bounds__(256) void cell0_mma(const float* __restrict__ hidden, int t)
{
    extern __shared__ char smem[];
    const float* __restrict__ hprev = (t == 0) ? hidden : g_h[11];
    const int nblk = blockIdx.x;
    const int n0 = nblk * 16;
    float acc[2][3][4] = {};
    run_tma_pipeline<1>(smem,
        [&](int ch, u32 st, u32 mb) {
            tma_bulk(st,         g_hhi[11] + ch * 8192, 16384, mb);
            tma_bulk(st + 16384, g_hlo[11] + ch * 8192, 16384, mb);
            size_t to = ((size_t)nblk * 8 + ch) * 2048;
            tma_bulk(st + 32768,        g_wxhh_hi + to, 4096, mb);
            tma_bulk(st + 32768 + 4096, g_wxch_hi + to, 4096, mb);
            tma_bulk(st + 40960,        g_wxhh_lo + to, 4096, mb);
            tma_bulk(st + 40960 + 4096, g_wxch_lo + to, 4096, mb);
        }, acc);

    float* ex = (float*)smem;
    const int lane = threadIdx.x & 31;
    const int mw = (threadIdx.x >> 5) & 3, ng = threadIdx.x >> 7;
    const int g = lane >> 2, tq = lane & 3;
    if (ng == 1) ex_store(ex, acc, mw, lane);    // c0 pre-activation sums
    __syncthreads();
    if (ng == 0) {
#pragma unroll
        for (int jj = 0; jj < 2; jj++)
#pragma unroll
            for (int r = 0; r < 2; r++) {
                const int m = 16 * mw + g + 8 * r;
                const int n = n0 + jj * 8 + 2 * tq;
                if (n < Hd) {
                    const int idx = m * Hd + n;
                    const size_t pidx = (size_t)(t * Bb + m) * Hd + n;
                    float2 sc = *(const float2*)&ex[(16 * mw + g + 8 * r) * 16 + jj * 8 + 2 * tq];
                    float2 ph = *(const float2*)&g_Ph[pidx];
                    float2 pc = *(const float2*)&g_Pc[pidx];
                    float2 hp = *(const float2*)&hprev[idx];
                    float c0a = sigmf(sc.x + pc.x);
                    float c0b = sigmf(sc.y + pc.y);
                    float h0a = c0a * tanhf(ASUM(jj, 2 * r) + ph.x) + (1.0f - c0a) * hp.x;
                    float h0b = c0b * tanhf(ASUM(jj, 2 * r + 1) + ph.y) + (1.0f - c0b) * hp.y;
                    *(float2*)&g_c0[idx] = make_float2(c0a, c0b);
                    *(float2*)&g_h[0][idx] = make_float2(h0a, h0b);
                    bf16 ha, la, hb, lb;
                    split1(h0a, ha, la); split1(h0b, hb, lb);
                    const size_t so = chmaj_off(m, n);
                    *(u32*)&g_hhi[0][so] = b2u(ha, hb);
                    *(u32*)&g_hlo[0][so] = b2u(la, lb);

                    if (t > 0) {   // fused leaf mean for step t-1 (hp = h11(t-1))
                        float2 h5 = *(const float2*)&g_h[5][idx];
                        float2 h7 = *(const float2*)&g_h[7][idx];
                        float2 h8 = *(const float2*)&g_h[8][idx];
                        float2 h9 = *(const float2*)&g_h[9][idx];
                        float2 hA = *(const float2*)&g_h[10][idx];
                        float oa = (h5.x + h7.x + h8.x + h9.x + hA.x + hp.x) * (1.0f / 6.0f);
                        float ob = (h5.y + h7.y + h8.y + h9.y + hA.y + hp.y) * (1.0f / 6.0f);
                        split1(oa, ha, la); split1(ob, hb, lb);
                        const size_t oo = (size_t)(t - 1) * HCH + so;
                        *(u32*)&g_outshi[oo] = b2u(ha, hb);
                        *(u32*)&g_outslo[oo] = b2u(la, lb);
                    }
                }
            }
    }
}

// ---------------------------------------------------------------------------
// Generic DAG level. grid = (63, n_edges).
// ---------------------------------------------------------------------------
__global__ __launch_bounds__(256) void level_mma(LevelDesc L)
{
    extern __shared__ char smem[];
    const EdgeDesc ed = L.e[blockIdx.y];
    const float* __restrict__ hin = g_h[ed.parent];
    float* __restrict__ hout = g_h[ed.child];
    const bf16* ahi = g_hhi[ed.parent];
    const bf16* alo = g_hlo[ed.parent];
    const size_t wb = (size_t)ed.w * TILEMAT;
    const int nblk = blockIdx.x;
    const int n0 = nblk * 16;

    float acc[2][3][4] = {};
    run_tma_pipeline<1>(smem,
        [&](int ch, u32 st, u32 mb) {
            tma_bulk(st,         ahi + ch * 8192, 16384, mb);
            tma_bulk(st + 16384, alo + ch * 8192, 16384, mb);
            size_t to = wb + ((size_t)nblk * 8 + ch) * 2048;
            tma_bulk(st + 32768,        g_Whhi + to, 4096, mb);
            tma_bulk(st + 32768 + 4096, g_Wchi + to, 4096, mb);
            tma_bulk(st + 40960,        g_Whlo + to, 4096, mb);
            tma_bulk(st + 40960 + 4096, g_Wclo + to, 4096, mb);
        }, acc);

    float* ex = (float*)smem;
    const int lane = threadIdx.x & 31;
    const int mw = (threadIdx.x >> 5) & 3, ng = threadIdx.x >> 7;
    const int g = lane >> 2, tq = lane & 3;
    if (ng == 1) ex_store(ex, acc, mw, lane);    // Wc sums
    __syncthreads();
    if (ng == 0) {
#pragma unroll
        for (int jj = 0; jj < 2; jj++)
#pragma unroll
            for (int r = 0; r < 2; r++) {
                const int m = 16 * mw + g + 8 * r;
                const int n = n0 + jj * 8 + 2 * tq;
                if (n < Hd) {
                    const int idx = m * Hd + n;
                    float2 sc = *(const float2*)&ex[(16 * mw + g + 8 * r) * 16 + jj * 8 + 2 * tq];
                    float2 hi2 = *(const float2*)&hin[idx];
                    float2 c02 = *(const float2*)&g_c0[idx];
                    float oa = sigmf(sc.x) * applyAct(ed.act, ASUM(jj, 2 * r))
                               + (1.0f - c02.x) * hi2.x;
                    float ob = sigmf(sc.y) * applyAct(ed.act, ASUM(jj, 2 * r + 1))
                               + (1.0f - c02.y) * hi2.y;
                    *(float2*)&hout[idx] = make_float2(oa, ob);
                    if (ed.split) {
                        bf16 ha, la, hb, lb;
                        split1(oa, ha, la); split1(ob, hb, lb);
                        const size_t so = chmaj_off(m, n);
                        *(u32*)&g_hhi[ed.child][so] = b2u(ha, hb);
                        *(u32*)&g_hlo[ed.child][so] = b2u(la, lb);
                    }
                }
            }
    }
}

// ---------------------------------------------------------------------------
// Tail leaf mean (t = 63 only).
// ---------------------------------------------------------------------------
__global__ __launch_bounds__(256) void mean_kernel(int t)
{
    int i = blockIdx.x * 256 + threadIdx.x;
    if (i < Bb * Hd / 2) {
        int idx = 2 * i;
        int m = idx / Hd, n = idx % Hd;
        float s0 = (g_h[5][idx] + g_h[7][idx] + g_h[8][idx] + g_h[9][idx]
                    + g_h[10][idx] + g_h[11][idx]) * (1.0f / 6.0f);
        float s1 = (g_h[5][idx + 1] + g_h[7][idx + 1] + g_h[8][idx + 1] + g_h[9][idx + 1]
                    + g_h[10][idx + 1] + g_h[11][idx + 1]) * (1.0f / 6.0f);
        bf16 h0, l0, h1, l1;
        split1(s0, h0, l0); split1(s1, h1, l1);
        size_t o = (size_t)t * HCH + chmaj_off(m, n);
        *(u32*)&g_outshi[o] = b2u(h0, h1);
        *(u32*)&g_outslo[o] = b2u(l0, l1);
    }
}

// ---------------------------------------------------------------------------
// Decoder: out[m][v] = outs[m] . dec_w[v] + dec_b[v]; grid (313, 64).
// ---------------------------------------------------------------------------
__global__ __launch_bounds__(256) void decoder_mma(
    const float* __restrict__ dec_b, float* __restrict__ out)
{
    extern __shared__ char smem[];
    const int t = blockIdx.y;
    const int n0 = blockIdx.x * 32;
    const int nb0 = blockIdx.x * 2;
    const bf16* ahi = g_outshi + (size_t)t * HCH;
    const bf16* alo = g_outslo + (size_t)t * HCH;

    float acc[2][3][4] = {};
    run_tma_pipeline<1>(smem,
        [&](int ch, u32 st, u32 mb) {
            tma_bulk(st,         ahi + ch * 8192, 16384, mb);
            tma_bulk(st + 16384, alo + ch * 8192, 16384, mb);
            size_t t0 = ((size_t)nb0 * 8 + ch) * 2048;
            size_t t1 = ((size_t)(nb0 + 1) * 8 + ch) * 2048;
            tma_bulk(st + 32768,        g_dect_hi + t0, 4096, mb);
            tma_bulk(st + 32768 + 4096, g_dect_hi + t1, 4096, mb);
            tma_bulk(st + 40960,        g_dect_lo + t0, 4096, mb);
            tma_bulk(st + 40960 + 4096, g_dect_lo + t1, 4096, mb);
        }, acc);

    const int lane = threadIdx.x & 31;
    const int mw = (threadIdx.x >> 5) & 3, ng = threadIdx.x >> 7;
    const int g = lane >> 2, tq = lane & 3;
    const int m0 = t * 64;
#pragma unroll
    for (int jj = 0; jj < 2; jj++)
#pragma unroll
        for (int r = 0; r < 2; r++) {
            const int m = m0 + 16 * mw + g + 8 * r;
            const int n = n0 + ng * 16 + jj * 8 + 2 * tq;
            if (n < Vv) {
                float2 db = *(const float2*)&dec_b[n];
                *(float2*)&out[(size_t)m * Vv + n] =
                    make_float2(ASUM(jj, 2 * r) + db.x, ASUM(jj, 2 * r + 1) + db.y);
            }
        }
}

} // namespace

// ---------------------------------------------------------------------------
extern "C" void kernel_launch(void* const* d_in, const int* in_sizes, int n_in,
                              void* d_out, int out_size)
{
    (void)in_sizes; (void)n_in; (void)out_size;

    const int*   inputs = (const int*)  d_in[0];
    const float* hidden = (const float*)d_in[1];
    const float* emb    = (const float*)d_in[2];
    const float* w_xh   = (const float*)d_in[3];
    const float* b_xh   = (const float*)d_in[4];
    const float* w_xc   = (const float*)d_in[5];
    const float* b_xc   = (const float*)d_in[6];
    const float* Wh     = (const float*)d_in[7];
    const float* Wc     = (const float*)d_in[8];
    const float* dec_w  = (const float*)d_in[9];
    const float* dec_b  = (const float*)d_in[10];
    float* out = (float*)d_out;

    cudaFuncSetAttribute(precomp_mma, cudaFuncAttributeMaxDynamicSharedMemorySize, SMEM_T);
    cudaFuncSetAttribute(cell0_mma,   cudaFuncAttributeMaxDynamicSharedMemorySize, SMEM_T);
    cudaFuncSetAttribute(level_mma,   cudaFuncAttributeMaxDynamicSharedMemorySize, SMEM_T);
    cudaFuncSetAttribute(decoder_mma, cudaFuncAttributeMaxDynamicSharedMemorySize, SMEM_T);

    // acts: 0=relu, 1=tanh, 2=sigmoid, 3=identity; split=1 if child is a parent
    const LevelDesc LV1 = {{ {0, 1, 0, 0, 1},  {0, 6, 1, 1, 1},  {0, 0, 0, 3, 0} }};
    const LevelDesc LV2 = {{ {1, 2, 2, 0, 1},  {1, 8, 3, 2, 0},  {6, 7, 10, 1, 0} }};
    const LevelDesc LV3 = {{ {2, 3, 4, 1, 1},  {2, 9, 5, 0, 0},  {0, 0, 0, 3, 0} }};
    const LevelDesc LV4 = {{ {3, 4, 6, 3, 1},  {3, 10, 7, 1, 0}, {0, 0, 0, 3, 0} }};
    const LevelDesc LV5 = {{ {4, 5, 8, 0, 0},  {4, 11, 9, 2, 1}, {0, 0, 0, 3, 0} }};

    prep_split<<<(PREP_UNITS + 255) / 256, 256>>>(Wh, Wc, dec_w, emb, hidden, w_xh, w_xc);
    precomp_mma<<<dim3(63, 64), 256, SMEM_T>>>(inputs, b_xh, b_xc);

    for (int t = 0; t < Tt; ++t) {
        cell0_mma<<<63, 256, SMEM_T>>>(hidden, t);   // also emits mean(t-1)
        level_mma<<<dim3(63, 2), 256, SMEM_T>>>(LV1);
        level_mma<<<dim3(63, 3), 256, SMEM_T>>>(LV2);
        level_mma<<<dim3(63, 2), 256, SMEM_T>>>(LV3);
        level_mma<<<dim3(63, 2), 256, SMEM_T>>>(LV4);
        level_mma<<<dim3(63, 2), 256, SMEM_T>>>(LV5);
    }
    mean_kernel<<<(Bb * Hd / 2 + 255) / 256, 256>>>(Tt - 1);   // tail mean

    decoder_mma<<<dim3(313, 64), 256, SMEM_T>>>(dec_b, out);
}